// round 13
// baseline (speedup 1.0000x reference)
#include <cuda_runtime.h>
#include <cuda_bf16.h>

// loss = sum_{pos} softplus(-p)/n_pos + sum_{neg} softplus(p)/n_neg
// over 8192x8192 f32 + i32. Streaming reduction at the HBM/LTS cap.
// R12: harvest the ~10us CTA finish spread (measured via R11's stage2 window)
// using the HW scheduler's wave>=2 work-stealing: 16384 blocks x 128 thr
// (~6.9 waves, T_CTA ~11us) with a STATIC uniform partition (2^24 / 2^21 =
// exactly 8 iterations per thread -> deterministic partials independent of
// CTA placement/timing). Slow SMs simply run fewer CTAs; tail cost drops
// from slowness*T_kernel (~8us) to slowness*T_CTA (~1us).
// Epilogue: R9's proven-best join (PDL + grid-dependency-sync stage2).

#define NBLOCKS  16384
#define NTHREADS 128
#define N_TOTAL  67108864    // 8192*8192
#define N_VEC4   16777216    // 2^24 float4
#define STRIDE   (NBLOCKS * NTHREADS)   // 2^21 -> 8 uniform iterations
#define NITER    (N_VEC4 / STRIDE)      // 8

__device__ float g_pos[NBLOCKS];
__device__ float g_neg[NBLOCKS];
__device__ int   g_cnt[NBLOCKS];

// softplus(x)  = log1p(e^{-|x|}) + max(x, 0)
// softplus(-x) = log1p(e^{-|x|}) + max(-x, 0)
// -> one EX2 + one LG2 per element regardless of label.
__device__ __forceinline__ void lane_accum(float x, int y,
                                           float& pos, float& neg, int& cnt) {
    float ax     = fabsf(x);
    float common = __logf(1.0f + __expf(-ax));
    bool  ispos  = (y != 0);
    float relu   = fmaxf(ispos ? -x : x, 0.0f);
    float v      = common + relu;
    pos += ispos ? v : 0.0f;
    neg += ispos ? 0.0f : v;
    cnt += ispos ? 1 : 0;
}

__global__ __launch_bounds__(NTHREADS)
void reduce_stage1(const float4* __restrict__ pred,
                   const int4*  __restrict__ ty) {
    float pos = 0.0f, neg = 0.0f;
    int   cnt = 0;

    // Exactly NITER uniform iterations; 2 LDG.128 per warp-iteration
    // (measured-best load shape — chip MLP comes from warp count).
    int i = blockIdx.x * NTHREADS + threadIdx.x;
    #pragma unroll
    for (int k = 0; k < NITER; k++, i += STRIDE) {
        float4 p = __ldcs(pred + i);   // streaming: touched once
        int4   y = __ldcs(ty + i);
        lane_accum(p.x, y.x, pos, neg, cnt);
        lane_accum(p.y, y.y, pos, neg, cnt);
        lane_accum(p.z, y.z, pos, neg, cnt);
        lane_accum(p.w, y.w, pos, neg, cnt);
    }

    // Block reduction (fixed tree -> deterministic)
    #pragma unroll
    for (int o = 16; o > 0; o >>= 1) {
        pos += __shfl_down_sync(0xFFFFFFFFu, pos, o);
        neg += __shfl_down_sync(0xFFFFFFFFu, neg, o);
        cnt += __shfl_down_sync(0xFFFFFFFFu, cnt, o);
    }
    __shared__ float sp[NTHREADS / 32];
    __shared__ float sn[NTHREADS / 32];
    __shared__ int   sc[NTHREADS / 32];
    int wid = threadIdx.x >> 5;
    int lid = threadIdx.x & 31;
    if (lid == 0) { sp[wid] = pos; sn[wid] = neg; sc[wid] = cnt; }
    __syncthreads();

    if (threadIdx.x == 0) {
        constexpr int NW = NTHREADS / 32;
        float bp = 0.0f, bn = 0.0f; int bc = 0;
        #pragma unroll
        for (int w = 0; w < NW; w++) { bp += sp[w]; bn += sn[w]; bc += sc[w]; }
        g_pos[blockIdx.x] = bp;
        g_neg[blockIdx.x] = bn;
        g_cnt[blockIdx.x] = bc;
    }
    __syncthreads();
    // PDL: stage2's launch/ramp overlaps this grid's drain.
    cudaTriggerProgrammaticLaunchCompletion();
}

__global__ __launch_bounds__(1024)
void reduce_stage2(float* __restrict__ out) {
    // Gate on stage1 grid completion under PDL; no-op otherwise.
    cudaGridDependencySynchronize();

    float pos = 0.0f, neg = 0.0f;
    int   cnt = 0;
    for (int i = threadIdx.x; i < NBLOCKS; i += 1024) {
        pos += g_pos[i];
        neg += g_neg[i];
        cnt += g_cnt[i];
    }
    #pragma unroll
    for (int o = 16; o > 0; o >>= 1) {
        pos += __shfl_down_sync(0xFFFFFFFFu, pos, o);
        neg += __shfl_down_sync(0xFFFFFFFFu, neg, o);
        cnt += __shfl_down_sync(0xFFFFFFFFu, cnt, o);
    }
    __shared__ float sp[32];
    __shared__ float sn[32];
    __shared__ int   sc[32];
    int wid = threadIdx.x >> 5;
    int lid = threadIdx.x & 31;
    if (lid == 0) { sp[wid] = pos; sn[wid] = neg; sc[wid] = cnt; }
    __syncthreads();
    if (wid == 0) {
        float bp = sp[lid];
        float bn = sn[lid];
        int   bc = sc[lid];
        #pragma unroll
        for (int o = 16; o > 0; o >>= 1) {
            bp += __shfl_down_sync(0xFFFFFFFFu, bp, o);
            bn += __shfl_down_sync(0xFFFFFFFFu, bn, o);
            bc += __shfl_down_sync(0xFFFFFFFFu, bc, o);
        }
        if (lid == 0) {
            float n_pos = (float)bc;
            float n_neg = (float)(N_TOTAL - bc);
            out[0] = bp / n_pos + bn / n_neg;
        }
    }
}

extern "C" void kernel_launch(void* const* d_in, const int* in_sizes, int n_in,
                              void* d_out, int out_size) {
    const float4* pred = (const float4*)d_in[0];  // pred_y: float32 [8192,8192]
    const int4*   ty   = (const int4*)  d_in[1];  // true_y: int32   [8192,8192]
    float*        out  = (float*)d_out;

    reduce_stage1<<<NBLOCKS, NTHREADS>>>(pred, ty);

    // Stage2 with PDL so its launch/ramp overlaps stage1's drain.
    cudaLaunchConfig_t cfg = {};
    cfg.gridDim  = dim3(1, 1, 1);
    cfg.blockDim = dim3(1024, 1, 1);
    cfg.dynamicSmemBytes = 0;
    cfg.stream = 0;
    cudaLaunchAttribute attr;
    attr.id = cudaLaunchAttributeProgrammaticStreamSerialization;
    attr.val.programmaticStreamSerializationAllowed = 1;
    cfg.attrs = &attr;
    cfg.numAttrs = 1;

    cudaError_t err = cudaLaunchKernelEx(&cfg, reduce_stage2, out);
    if (err != cudaSuccess) {
        (void)cudaGetLastError();            // clear sticky error
        reduce_stage2<<<1, 1024>>>(out);     // plain fallback (stream order)
    }
}

// round 14
// speedup vs baseline: 1.0170x; 1.0170x over previous
#include <cuda_runtime.h>
#include <cuda_bf16.h>

// loss = sum_{pos} softplus(-p)/n_pos + sum_{neg} softplus(p)/n_neg
// over 8192x8192 f32 + i32. Streaming reduction at the LTS cap (~77us floor
// incl. ~10us stochastic CTA finish spread — measured, unfixable).
// R13: R11's hook-style overlap (stage2 resident DURING stage1, syncing on
// per-block flags) but polling with __nanosleep backoff instead of a hot
// volatile-LDG spin. R11's regression was LSU starvation of co-resident
// streaming CTAs; a sleeping warp issues nothing, so that mechanism is gone.
//   stage1: R9 loop verbatim; PDL trigger at START (grid = one full wave,
//           resident at T=0); publish partial + release-store private flag.
//   stage2: sleep-poll 1184 flags -> fence -> fixed-order reduce -> reset
//           flags (replay-safe) -> out[0]. Plain-launch fallback correct.

#define NBLOCKS  1184        // 148 SMs * 8 CTAs = exactly one wave
#define NTHREADS 256
#define N_TOTAL  67108864    // 8192*8192
#define N_VEC4   16777216    // N_TOTAL / 4

__device__ float g_pos[NBLOCKS];
__device__ float g_neg[NBLOCKS];
__device__ int   g_cnt[NBLOCKS];
__device__ int   g_flag[NBLOCKS];   // zero-init; stage2 resets after consuming

// softplus(x)  = log1p(e^{-|x|}) + max(x, 0)
// softplus(-x) = log1p(e^{-|x|}) + max(-x, 0)
// -> one EX2 + one LG2 per element regardless of label.
__device__ __forceinline__ void lane_accum(float x, int y,
                                           float& pos, float& neg, int& cnt) {
    float ax     = fabsf(x);
    float common = __logf(1.0f + __expf(-ax));
    bool  ispos  = (y != 0);
    float relu   = fmaxf(ispos ? -x : x, 0.0f);
    float v      = common + relu;
    pos += ispos ? v : 0.0f;
    neg += ispos ? 0.0f : v;
    cnt += ispos ? 1 : 0;
}

__global__ __launch_bounds__(NTHREADS)
void reduce_stage1(const float4* __restrict__ pred,
                   const int4*  __restrict__ ty) {
    // Whole grid is resident at T=0 (one wave): fire PDL immediately so
    // stage2 can occupy the first freed slot (~67us in) and sleep-poll.
    cudaTriggerProgrammaticLaunchCompletion();

    float pos = 0.0f, neg = 0.0f;
    int   cnt = 0;

    // Measured-best loop shape (R1/R9): 2 LDG.128 per warp-iteration,
    // chip MLP from 64 warps/SM. Do not touch.
    const int stride = gridDim.x * blockDim.x;
    for (int i = blockIdx.x * blockDim.x + threadIdx.x; i < N_VEC4; i += stride) {
        float4 p = __ldcs(pred + i);   // streaming: touched once
        int4   y = __ldcs(ty + i);
        lane_accum(p.x, y.x, pos, neg, cnt);
        lane_accum(p.y, y.y, pos, neg, cnt);
        lane_accum(p.z, y.z, pos, neg, cnt);
        lane_accum(p.w, y.w, pos, neg, cnt);
    }

    // Block reduction (fixed tree -> deterministic)
    #pragma unroll
    for (int o = 16; o > 0; o >>= 1) {
        pos += __shfl_down_sync(0xFFFFFFFFu, pos, o);
        neg += __shfl_down_sync(0xFFFFFFFFu, neg, o);
        cnt += __shfl_down_sync(0xFFFFFFFFu, cnt, o);
    }
    __shared__ float sp[NTHREADS / 32];
    __shared__ float sn[NTHREADS / 32];
    __shared__ int   sc[NTHREADS / 32];
    int wid = threadIdx.x >> 5;
    int lid = threadIdx.x & 31;
    if (lid == 0) { sp[wid] = pos; sn[wid] = neg; sc[wid] = cnt; }
    __syncthreads();

    if (threadIdx.x == 0) {
        constexpr int NW = NTHREADS / 32;
        float bp = 0.0f, bn = 0.0f; int bc = 0;
        #pragma unroll
        for (int w = 0; w < NW; w++) { bp += sp[w]; bn += sn[w]; bc += sc[w]; }
        g_pos[blockIdx.x] = bp;
        g_neg[blockIdx.x] = bn;
        g_cnt[blockIdx.x] = bc;
        __threadfence();                              // release partials
        *(volatile int*)&g_flag[blockIdx.x] = 1;      // private flag
    }
}

__global__ __launch_bounds__(NTHREADS)
void reduce_stage2(float* __restrict__ out) {
    // Data-level sync with sleep backoff: wait for every block's flag
    // without pressuring the LSU of co-resident streaming CTAs.
    for (int k = threadIdx.x; k < NBLOCKS; k += NTHREADS) {
        while (*(volatile int*)&g_flag[k] == 0) {
            __nanosleep(128);
        }
    }
    __syncthreads();
    __threadfence();   // acquire: all partials visible

    float fp = 0.0f, fn = 0.0f; int fc = 0;
    for (int k = threadIdx.x; k < NBLOCKS; k += NTHREADS) {
        fp += g_pos[k]; fn += g_neg[k]; fc += g_cnt[k];
        g_flag[k] = 0;                 // reset for next graph replay
    }
    #pragma unroll
    for (int o = 16; o > 0; o >>= 1) {
        fp += __shfl_down_sync(0xFFFFFFFFu, fp, o);
        fn += __shfl_down_sync(0xFFFFFFFFu, fn, o);
        fc += __shfl_down_sync(0xFFFFFFFFu, fc, o);
    }
    __shared__ float sp[NTHREADS / 32];
    __shared__ float sn[NTHREADS / 32];
    __shared__ int   sc[NTHREADS / 32];
    int wid = threadIdx.x >> 5;
    int lid = threadIdx.x & 31;
    if (lid == 0) { sp[wid] = fp; sn[wid] = fn; sc[wid] = fc; }
    __syncthreads();
    if (threadIdx.x == 0) {
        constexpr int NW = NTHREADS / 32;
        float bp = 0.0f, bn = 0.0f; int bc = 0;
        #pragma unroll
        for (int w = 0; w < NW; w++) { bp += sp[w]; bn += sn[w]; bc += sc[w]; }
        float n_pos = (float)bc;
        float n_neg = (float)(N_TOTAL - bc);
        out[0] = bp / n_pos + bn / n_neg;
    }
}

extern "C" void kernel_launch(void* const* d_in, const int* in_sizes, int n_in,
                              void* d_out, int out_size) {
    const float4* pred = (const float4*)d_in[0];  // pred_y: float32 [8192,8192]
    const int4*   ty   = (const int4*)  d_in[1];  // true_y: int32   [8192,8192]
    float*        out  = (float*)d_out;

    reduce_stage1<<<NBLOCKS, NTHREADS>>>(pred, ty);

    // Launch stage2 with PDL so it becomes resident DURING stage1 and syncs
    // on the flags (data), not the kernel boundary.
    cudaLaunchConfig_t cfg = {};
    cfg.gridDim  = dim3(1, 1, 1);
    cfg.blockDim = dim3(NTHREADS, 1, 1);
    cfg.dynamicSmemBytes = 0;
    cfg.stream = 0;
    cudaLaunchAttribute attr;
    attr.id = cudaLaunchAttributeProgrammaticStreamSerialization;
    attr.val.programmaticStreamSerializationAllowed = 1;
    cfg.attrs = &attr;
    cfg.numAttrs = 1;

    cudaError_t err = cudaLaunchKernelEx(&cfg, reduce_stage2, out);
    if (err != cudaSuccess) {
        (void)cudaGetLastError();          // clear sticky error
        // Plain fallback: runs after stage1; flags already set, poll exits
        // immediately. Correct either way.
        reduce_stage2<<<1, NTHREADS>>>(out);
    }
}

// round 15
// speedup vs baseline: 1.0496x; 1.0320x over previous
#include <cuda_runtime.h>
#include <cuda_bf16.h>

// loss = sum_{pos} softplus(-p)/n_pos + sum_{neg} softplus(p)/n_neg
// over 8192x8192 f32 + i32. Streaming reduction at the streaming cap.
// R14 = R9 verbatim (measured session-best, 82.7us). Rationale:
//  - Load shapes (R1/R3/R5/R8) all land in the 6.0-6.7 TB/s cap band ->
//    loop-shape tuning is noise; R1's shape kept.
//  - Epilogue designs measured: fused ticket/flags 86-88, multi-wave 86,
//    overlap-poll 84.3-84.6, plain split 83.3, split+PDL 82.7 (best).
//    The kernel boundary beats every software join against a cap-bound
//    stream; flag/fence epilogues perturb T_last by ~2us.
//  - Remaining gap to stage1 floor (~5us) = stochastic CTA finish spread
//    (~10us, measured in R11/R12, unfixable) + launch mechanics.

#define NBLOCKS  1184        // 148 SMs * 8 CTAs, one full wave
#define NTHREADS 256
#define N_TOTAL  67108864    // 8192*8192
#define N_VEC4   16777216    // N_TOTAL / 4

__device__ float g_pos[NBLOCKS];
__device__ float g_neg[NBLOCKS];
__device__ int   g_cnt[NBLOCKS];

// softplus(x)  = log1p(e^{-|x|}) + max(x, 0)
// softplus(-x) = log1p(e^{-|x|}) + max(-x, 0)
// -> one EX2 + one LG2 per element regardless of label.
__device__ __forceinline__ void lane_accum(float x, int y,
                                           float& pos, float& neg, int& cnt) {
    float ax     = fabsf(x);
    float common = __logf(1.0f + __expf(-ax));
    bool  ispos  = (y != 0);
    float relu   = fmaxf(ispos ? -x : x, 0.0f);
    float v      = common + relu;
    pos += ispos ? v : 0.0f;
    neg += ispos ? 0.0f : v;
    cnt += ispos ? 1 : 0;
}

__global__ __launch_bounds__(NTHREADS)
void reduce_stage1(const float4* __restrict__ pred,
                   const int4*  __restrict__ ty) {
    float pos = 0.0f, neg = 0.0f;
    int   cnt = 0;

    // Measured-best loop shape: 2 LDG.128 per warp-iteration; chip MLP
    // comes from 64 warps/SM. Do not touch.
    const int stride = gridDim.x * blockDim.x;
    for (int i = blockIdx.x * blockDim.x + threadIdx.x; i < N_VEC4; i += stride) {
        float4 p = __ldcs(pred + i);   // streaming: touched once
        int4   y = __ldcs(ty + i);
        lane_accum(p.x, y.x, pos, neg, cnt);
        lane_accum(p.y, y.y, pos, neg, cnt);
        lane_accum(p.z, y.z, pos, neg, cnt);
        lane_accum(p.w, y.w, pos, neg, cnt);
    }

    // Block reduction (fixed tree -> deterministic)
    #pragma unroll
    for (int o = 16; o > 0; o >>= 1) {
        pos += __shfl_down_sync(0xFFFFFFFFu, pos, o);
        neg += __shfl_down_sync(0xFFFFFFFFu, neg, o);
        cnt += __shfl_down_sync(0xFFFFFFFFu, cnt, o);
    }

    __shared__ float sp[NTHREADS / 32];
    __shared__ float sn[NTHREADS / 32];
    __shared__ int   sc[NTHREADS / 32];
    int wid = threadIdx.x >> 5;
    int lid = threadIdx.x & 31;
    if (lid == 0) { sp[wid] = pos; sn[wid] = neg; sc[wid] = cnt; }
    __syncthreads();

    if (wid == 0) {
        constexpr int NW = NTHREADS / 32;
        float bp = (lid < NW) ? sp[lid] : 0.0f;
        float bn = (lid < NW) ? sn[lid] : 0.0f;
        int   bc = (lid < NW) ? sc[lid] : 0;
        #pragma unroll
        for (int o = NW / 2; o > 0; o >>= 1) {
            bp += __shfl_down_sync(0xFFFFFFFFu, bp, o);
            bn += __shfl_down_sync(0xFFFFFFFFu, bn, o);
            bc += __shfl_down_sync(0xFFFFFFFFu, bc, o);
        }
        if (lid == 0) {
            g_pos[blockIdx.x] = bp;
            g_neg[blockIdx.x] = bn;
            g_cnt[blockIdx.x] = bc;
        }
    }
    __syncthreads();
    // Partials published; let the PDL-dependent stage2 proceed once every
    // block has triggered (stage2 launch/ramp overlaps this grid's drain).
    cudaTriggerProgrammaticLaunchCompletion();
}

__global__ __launch_bounds__(1024)
void reduce_stage2(float* __restrict__ out) {
    // Gate on stage1 completion under PDL; documented no-op otherwise.
    cudaGridDependencySynchronize();

    float pos = 0.0f, neg = 0.0f;
    int   cnt = 0;
    for (int i = threadIdx.x; i < NBLOCKS; i += 1024) {
        pos += g_pos[i];
        neg += g_neg[i];
        cnt += g_cnt[i];
    }
    #pragma unroll
    for (int o = 16; o > 0; o >>= 1) {
        pos += __shfl_down_sync(0xFFFFFFFFu, pos, o);
        neg += __shfl_down_sync(0xFFFFFFFFu, neg, o);
        cnt += __shfl_down_sync(0xFFFFFFFFu, cnt, o);
    }
    __shared__ float sp[32];
    __shared__ float sn[32];
    __shared__ int   sc[32];
    int wid = threadIdx.x >> 5;
    int lid = threadIdx.x & 31;
    if (lid == 0) { sp[wid] = pos; sn[wid] = neg; sc[wid] = cnt; }
    __syncthreads();
    if (wid == 0) {
        float bp = sp[lid];
        float bn = sn[lid];
        int   bc = sc[lid];
        #pragma unroll
        for (int o = 16; o > 0; o >>= 1) {
            bp += __shfl_down_sync(0xFFFFFFFFu, bp, o);
            bn += __shfl_down_sync(0xFFFFFFFFu, bn, o);
            bc += __shfl_down_sync(0xFFFFFFFFu, bc, o);
        }
        if (lid == 0) {
            float n_pos = (float)bc;
            float n_neg = (float)(N_TOTAL - bc);
            out[0] = bp / n_pos + bn / n_neg;
        }
    }
}

extern "C" void kernel_launch(void* const* d_in, const int* in_sizes, int n_in,
                              void* d_out, int out_size) {
    const float4* pred = (const float4*)d_in[0];  // pred_y: float32 [8192,8192]
    const int4*   ty   = (const int4*)  d_in[1];  // true_y: int32   [8192,8192]
    float*        out  = (float*)d_out;

    reduce_stage1<<<NBLOCKS, NTHREADS>>>(pred, ty);

    // Stage2 with PDL so its launch/ramp overlaps stage1's drain.
    cudaLaunchConfig_t cfg = {};
    cfg.gridDim  = dim3(1, 1, 1);
    cfg.blockDim = dim3(1024, 1, 1);
    cfg.dynamicSmemBytes = 0;
    cfg.stream = 0;
    cudaLaunchAttribute attr;
    attr.id = cudaLaunchAttributeProgrammaticStreamSerialization;
    attr.val.programmaticStreamSerializationAllowed = 1;
    cfg.attrs = &attr;
    cfg.numAttrs = 1;

    cudaError_t err = cudaLaunchKernelEx(&cfg, reduce_stage2, out);
    if (err != cudaSuccess) {
        (void)cudaGetLastError();            // clear sticky error
        reduce_stage2<<<1, 1024>>>(out);     // plain fallback (stream order)
    }
}